// round 9
// baseline (speedup 1.0000x reference)
#include <cuda_runtime.h>

#define BATCH 2
#define NBOX  1000
#define NCLS  80
#define NCAND 100
#define CAND  2048          // max filtered candidates per batch
#define BCAP  1024          // per-class staging capacity (<=1000 used)
#define NHIST 4096
#define TARGET 1200
#define PC 0.03125f         // stage only p >= 1/32 (bucket-aligned)

typedef unsigned long long u64;
typedef unsigned int u32;

// globals zero-initialized at load; every invocation self-cleans.
__device__ int    g_bcnt[BATCH * NCLS];            // per-class staged counts
__device__ u64    g_bstage[BATCH * NCLS * BCAP];   // per-class staged keys
__device__ u32    g_hist [BATCH * NHIST];          // candidate score histogram
__device__ u32    g_hist2[BATCH * NHIST];          // survivor score histogram
__device__ u32    g_tb[BATCH];                     // candidate threshold bucket
__device__ int    g_scnt2[BATCH];                  // survivor counts
__device__ u64    g_surv[BATCH * CAND];            // survivor keys
__device__ float4 g_cbox[BATCH * NCLS * BCAP];     // survivor boxes by (c, rank)
__device__ int    g_done1;                         // score completion counter
__device__ int    g_done2;                         // nms completion counter

// ---------------------------------------------------------------------------
// K1: softmax + stage + histogram; LAST BLOCK computes thresholds (g_tb)
// and zeroes g_hist. 250 blocks x 256 (one warp per (b, n)).
// ---------------------------------------------------------------------------
__global__ __launch_bounds__(256) void score_kernel(const float* __restrict__ cls) {
    __shared__ u32 wtot[8], cexc[8];
    __shared__ int s_t1, s_t2, s_last;

    int tid  = threadIdx.x;
    int w    = tid >> 5;
    int lane = tid & 31;
    int gw   = (blockIdx.x * blockDim.x + tid) >> 5;
    int b    = gw / NBOX, n = gw % NBOX;

    const float* lg = cls + (size_t)(b * NBOX + n) * 81;

    float v0 = lg[lane];
    float v1 = lg[lane + 32];
    bool  ok2 = (lane + 64) < 81;
    float v2 = ok2 ? lg[lane + 64] : -1e30f;

    float mx = fmaxf(fmaxf(v0, v1), v2);
    #pragma unroll
    for (int o = 16; o; o >>= 1) mx = fmaxf(mx, __shfl_xor_sync(0xffffffffu, mx, o));

    float e0 = expf(v0 - mx);
    float e1 = expf(v1 - mx);
    float e2 = ok2 ? expf(v2 - mx) : 0.f;

    float s = e0 + e1 + e2;
    #pragma unroll
    for (int o = 16; o; o >>= 1) s += __shfl_xor_sync(0xffffffffu, s, o);
    float inv = 1.f / s;

    float pr[3] = { e0 * inv, e1 * inv, e2 * inv };

    #pragma unroll
    for (int h = 0; h < 3; h++) {
        int idx = lane + 32 * h;                 // logit index 0..80
        float p = pr[h];
        if (idx >= 1 && idx <= 80 && p >= PC) {
            u32 sb = __float_as_uint(p);
            int ci = b * NCLS + (idx - 1);
            int pos = atomicAdd(&g_bcnt[ci], 1);  // < 1000 always
            g_bstage[(size_t)ci * BCAP + pos] = ((u64)sb << 10) | (u32)(1023 - n);
            atomicAdd(&g_hist[b * NHIST + (sb >> 19)], 1u);
        }
    }

    // ---- completion counter: last block computes thresholds ----
    __threadfence();
    if (tid == 0) {
        int d = atomicAdd(&g_done1, 1);
        s_last = (d == (int)gridDim.x - 1);
    }
    __syncthreads();
    if (!s_last) return;
    __threadfence();

    // 256 threads; 16 buckets per thread
    for (int bb = 0; bb < BATCH; bb++) {
        if (tid == 0) { s_t1 = 0; s_t2 = NHIST - 1; }
        __syncthreads();
        int base = bb * NHIST + tid * 16;
        u32 L = 0;
        #pragma unroll
        for (int q = 0; q < 16; q++) L += g_hist[base + q];

        u32 x = L;                                // warp inclusive suffix
        #pragma unroll
        for (int off = 1; off < 32; off <<= 1) {
            u32 t = __shfl_down_sync(0xffffffffu, x, off);
            if (lane + off < 32) x += t;
        }
        if (lane == 0) wtot[w] = x;
        __syncthreads();
        if (w == 0) {
            u32 y  = (lane < 8) ? wtot[lane] : 0u;
            u32 yi = y;
            #pragma unroll
            for (int off = 1; off < 8; off <<= 1) {
                u32 t = __shfl_down_sync(0xffffffffu, yi, off);
                if (lane + off < 8) yi += t;
            }
            if (lane < 8) cexc[lane] = yi - y;    // suffix over warps > this one
        }
        __syncthreads();
        u32 run = (x - L) + cexc[w];              // suffix strictly after chunk
        #pragma unroll
        for (int q = 15; q >= 0; q--) {
            u32 hh = g_hist[base + q];
            g_hist[base + q] = 0;                 // clean for next invocation
            u32 suf = run + hh;
            int v = tid * 16 + q;
            if (suf >= TARGET) atomicMax(&s_t1, v);
            if (suf <= CAND)   atomicMin(&s_t2, v);
            run = suf;
        }
        __syncthreads();
        if (tid == 0) g_tb[bb] = (u32)((s_t1 > s_t2) ? s_t1 : s_t2);
        __syncthreads();
    }
    if (tid == 0) g_done1 = 0;
}

// ---------------------------------------------------------------------------
// K2: per (b, class) — filter, sort, decode, greedy NMS, emit survivors.
// LAST BLOCK then does the global top-100 selection for both batches.
// grid = BATCH*NCLS, block = 128.
// ---------------------------------------------------------------------------
__global__ __launch_bounds__(128) void class_nms_kernel(
        const float* __restrict__ box,
        const float* __restrict__ anc,
        const float* __restrict__ info,
        float* __restrict__ out) {
    __shared__ u64 skey[CAND];                    // 16 KB (also used by epilogue)
    __shared__ float4 sbx[BCAP];                  // 16 KB
    __shared__ unsigned char sflag[BCAP];
    __shared__ u32 wtot[4], cexc[4];
    __shared__ int s_n, s_cnt, s_base, s_last, s_t1;

    int tid  = threadIdx.x;
    int w    = tid >> 5;
    int lane = tid & 31;
    int ci   = blockIdx.x;
    int b    = ci / NCLS;
    int c    = ci % NCLS;

    if (tid == 0) s_n = 0;
    __syncthreads();

    // filter staged keys by threshold bucket
    int m  = g_bcnt[ci];
    u32 tb = g_tb[b];
    for (int i = tid; i < m; i += 128) {
        u64 k = g_bstage[(size_t)ci * BCAP + i];
        if ((((u32)(k >> 10)) >> 19) >= tb) {
            int p = atomicAdd(&s_n, 1);
            skey[p] = k;
        }
    }
    __syncthreads();
    int n = s_n;
    if (tid == 0) g_bcnt[ci] = 0;                 // cleanup for next invocation

    if (n > 0) {
        // pad to pow2, bitonic sort descending (score, ~boxidx)
        int P = 32; while (P < n) P <<= 1;
        for (int e = tid; e < P; e += 128) if (e >= n) skey[e] = 0ull;
        for (unsigned k = 2; k <= (unsigned)P; k <<= 1) {
            for (unsigned j = k >> 1; j > 0; j >>= 1) {
                __syncthreads();
                for (int e = tid; e < P; e += 128) {
                    int ixj = e ^ (int)j;
                    if (ixj > e) {
                        u64 va = skey[e], vb = skey[ixj];
                        bool desc = ((e & (int)k) == 0);
                        if (desc ? (va < vb) : (va > vb)) { skey[e] = vb; skey[ixj] = va; }
                    }
                }
            }
        }
        __syncthreads();

        // decode boxes (rank order)
        float hmax = info[b * 5 + 0] - 1.f;
        float wmax = info[b * 5 + 1] - 1.f;
        for (int i = tid; i < n; i += 128) {
            u64 k = skey[i];
            int nb = 1023 - (int)(k & 0x3FFull);
            float4 a = *(const float4*)(anc + (size_t)(b * NBOX + nb) * 4);
            float ha  = a.z - a.x + 1.f;
            float wa  = a.w - a.y + 1.f;
            float cya = a.x + 0.5f * ha;
            float cxa = a.y + 0.5f * wa;
            float4 e = *(const float4*)(box +
                         ((size_t)(b * NBOX + nb) * 81 + (c + 1)) * 4);
            float cy = (e.x / 10.f) * ha + cya;
            float cx = (e.y / 10.f) * wa + cxa;
            float h  = expf(e.z / 5.f) * ha;
            float wd = expf(e.w / 5.f) * wa;
            float ymin = fminf(fmaxf(cy - 0.5f * h,        0.f), hmax);
            float ymax = fminf(fmaxf(cy + 0.5f * h - 1.f,  0.f), hmax);
            float xmin = fminf(fmaxf(cx - 0.5f * wd,       0.f), wmax);
            float xmax = fminf(fmaxf(cx + 0.5f * wd - 1.f, 0.f), wmax);
            sbx[i]   = make_float4(ymin, xmin, ymax, xmax);
            sflag[i] = 0;
        }
        __syncthreads();

        // greedy NMS: warp 0, serial over i, j-parallel over lanes
        if (tid < 32) {
            for (int i = 0; i < n - 1; i++) {
                if (sflag[i] == 0) {
                    float4 B = sbx[i];
                    float ai = (B.z - B.x) * (B.w - B.y);
                    for (int j = i + 1 + tid; j < n; j += 32) {
                        float4 C = sbx[j];
                        float iy = fmaxf(0.f, fminf(B.z, C.z) - fmaxf(B.x, C.x));
                        float ix = fmaxf(0.f, fminf(B.w, C.w) - fmaxf(B.y, C.y));
                        float inter = iy * ix;
                        float aj  = (C.z - C.x) * (C.w - C.y);
                        float iou = inter / fmaxf(ai + aj - inter, 1e-8f);
                        if (iou > 0.5f) sflag[j] = 1;
                    }
                }
                __syncwarp();
            }
        }
        __syncthreads();

        // reserve global survivor slots
        if (tid == 0) s_cnt = 0;
        __syncthreads();
        int my = 0;
        for (int e = tid; e < n; e += 128) if (!sflag[e]) my++;
        if (my) atomicAdd(&s_cnt, my);
        __syncthreads();
        if (tid == 0) s_base = atomicAdd(&g_scnt2[b], s_cnt);
        __syncthreads();
        if (tid == 0) s_cnt = 0;
        __syncthreads();

        // emit survivors: key (score desc, (c,rank) asc proxy), box, histogram
        for (int e = tid; e < n; e += 128) {
            if (!sflag[e]) {
                u32 sb   = (u32)(skey[e] >> 10);
                u32 flat = (u32)(c * BCAP + e);       // rank == true class rank
                int slot = atomicAdd(&s_cnt, 1);
                g_surv[b * CAND + s_base + slot] =
                    ((u64)sb << 18) | (u64)(0x3FFFFu ^ flat);
                g_cbox[(size_t)ci * BCAP + e] = sbx[e];
                atomicAdd(&g_hist2[b * NHIST + (sb >> 19)], 1u);
            }
        }
    }

    // ---- completion counter: last block does the final top-100 ----
    __threadfence();
    if (tid == 0) {
        int d = atomicAdd(&g_done2, 1);
        s_last = (d == (int)gridDim.x - 1);
    }
    __syncthreads();
    if (!s_last) return;
    __threadfence();

    // 128 threads; 32 buckets per thread
    for (int bb = 0; bb < BATCH; bb++) {
        if (tid == 0) { s_t1 = 0; s_n = 0; }
        __syncthreads();

        int base = bb * NHIST + tid * 32;
        u32 L = 0;
        for (int q = 0; q < 32; q++) L += g_hist2[base + q];

        u32 x = L;
        #pragma unroll
        for (int off = 1; off < 32; off <<= 1) {
            u32 t = __shfl_down_sync(0xffffffffu, x, off);
            if (lane + off < 32) x += t;
        }
        if (lane == 0) wtot[w] = x;
        __syncthreads();
        if (w == 0) {
            u32 y  = (lane < 4) ? wtot[lane] : 0u;
            u32 yi = y;
            #pragma unroll
            for (int off = 1; off < 4; off <<= 1) {
                u32 t = __shfl_down_sync(0xffffffffu, yi, off);
                if (lane + off < 4) yi += t;
            }
            if (lane < 4) cexc[lane] = yi - y;
        }
        __syncthreads();
        u32 run = (x - L) + cexc[w];
        for (int q = 31; q >= 0; q--) {
            u32 hh = g_hist2[base + q];
            g_hist2[base + q] = 0;                // clean for next invocation
            u32 suf = run + hh;
            if (suf >= NCAND) atomicMax(&s_t1, tid * 32 + q);
            run = suf;
        }
        __syncthreads();
        u32 tb2 = (u32)s_t1;

        // filter survivors above the bucket threshold
        int tot = g_scnt2[bb];
        for (int i = tid; i < tot; i += 128) {
            u64 k = g_surv[bb * CAND + i];
            if ((((u32)(k >> 18)) >> 19) >= tb2) {
                int p = atomicAdd(&s_n, 1);
                skey[p] = k;                      // <= CAND by construction
            }
        }
        __syncthreads();
        int nn = s_n;

        int P = 128; while (P < nn) P <<= 1;
        for (int e = tid; e < P; e += 128) if (e >= nn) skey[e] = 0ull;
        for (unsigned k = 2; k <= (unsigned)P; k <<= 1) {
            for (unsigned j = k >> 1; j > 0; j >>= 1) {
                __syncthreads();
                for (int e = tid; e < P; e += 128) {
                    int ixj = e ^ (int)j;
                    if (ixj > e) {
                        u64 va = skey[e], vb = skey[ixj];
                        bool desc = ((e & (int)k) == 0);
                        if (desc ? (va < vb) : (va > vb)) { skey[e] = vb; skey[ixj] = va; }
                    }
                }
            }
        }
        __syncthreads();

        if (tid < NCAND) {
            u64 kv   = skey[tid];
            u32 sb   = (u32)(kv >> 18);
            u32 flat = 0x3FFFFu ^ ((u32)kv & 0x3FFFFu);
            int cc   = (int)(flat >> 10);
            int rank = (int)(flat & (BCAP - 1));
            float4 bx = g_cbox[(size_t)(bb * NCLS + cc) * BCAP + rank];
            float* o = out + (size_t)(bb * NCAND + tid) * 6;
            o[0] = bx.x; o[1] = bx.y; o[2] = bx.z; o[3] = bx.w;
            o[4] = __uint_as_float(sb);
            o[5] = (float)(cc + 1);
        }
        if (tid == 0) g_scnt2[bb] = 0;
        __syncthreads();
    }
    if (tid == 0) g_done2 = 0;
}

// ---------------------------------------------------------------------------
extern "C" void kernel_launch(void* const* d_in, const int* in_sizes, int n_in,
                              void* d_out, int out_size) {
    const float* cls  = (const float*)d_in[0];
    const float* box  = (const float*)d_in[1];
    const float* anc  = (const float*)d_in[2];
    const float* info = (const float*)d_in[3];

    score_kernel<<<(BATCH * NBOX * 32 + 255) / 256, 256>>>(cls);
    class_nms_kernel<<<BATCH * NCLS, 128>>>(box, anc, info, (float*)d_out);
}

// round 10
// speedup vs baseline: 2.2048x; 2.2048x over previous
#include <cuda_runtime.h>

#define BATCH 2
#define NBOX  1000
#define NCLS  80
#define NCAND 100
#define CAND  2048          // max filtered candidates per batch
#define BCAP  1024          // per-class staging capacity (<=1000 used)
#define NB    128           // histogram buckets (score bits >>19, rebased)
#define HBASE 1952          // (0x3D000000 >> 19): bucket of p = 1/32
#define TARGET 1200
#define PC 0.03125f         // stage only p >= 1/32 (bucket-aligned)

typedef unsigned long long u64;
typedef unsigned int u32;

// globals zero-initialized at load; every invocation self-cleans.
__device__ int    g_bcnt[BATCH * NCLS];            // per-class staged counts
__device__ u64    g_bstage[BATCH * NCLS * BCAP];   // per-class staged keys
__device__ u32    g_hist [BATCH * NB];             // candidate score histogram
__device__ u32    g_hist2[BATCH * NB];             // survivor score histogram
__device__ int    g_scnt2[BATCH];                  // survivor counts
__device__ u64    g_surv[BATCH * CAND];            // survivor keys
__device__ float4 g_cbox[BATCH * NCLS * BCAP];     // survivor boxes by (c, rank)

__device__ __forceinline__ int bkt(u32 sb) {
    int v = (int)(sb >> 19) - HBASE;
    v = v < 0 ? 0 : v;
    return v > NB - 1 ? NB - 1 : v;
}

// ---------------------------------------------------------------------------
// K1: single-pass softmax; stage (score, ~boxidx) into per-class buckets;
// histogram score bits. One warp per (b, n). 250 blocks x 256.
// ---------------------------------------------------------------------------
__global__ __launch_bounds__(256) void score_kernel(const float* __restrict__ cls) {
    int gw   = (blockIdx.x * blockDim.x + threadIdx.x) >> 5;
    int lane = threadIdx.x & 31;
    if (gw >= BATCH * NBOX) return;
    int b = gw / NBOX, n = gw % NBOX;

    const float* lg = cls + (size_t)(b * NBOX + n) * 81;

    float v0 = lg[lane];
    float v1 = lg[lane + 32];
    bool  ok2 = (lane + 64) < 81;
    float v2 = ok2 ? lg[lane + 64] : -1e30f;

    float mx = fmaxf(fmaxf(v0, v1), v2);
    #pragma unroll
    for (int o = 16; o; o >>= 1) mx = fmaxf(mx, __shfl_xor_sync(0xffffffffu, mx, o));

    float e0 = expf(v0 - mx);
    float e1 = expf(v1 - mx);
    float e2 = ok2 ? expf(v2 - mx) : 0.f;

    float s = e0 + e1 + e2;
    #pragma unroll
    for (int o = 16; o; o >>= 1) s += __shfl_xor_sync(0xffffffffu, s, o);
    float inv = 1.f / s;

    float pr[3] = { e0 * inv, e1 * inv, e2 * inv };

    #pragma unroll
    for (int h = 0; h < 3; h++) {
        int idx = lane + 32 * h;                 // logit index 0..80
        float p = pr[h];
        if (idx >= 1 && idx <= 80 && p >= PC) {
            u32 sb = __float_as_uint(p);
            int ci = b * NCLS + (idx - 1);
            int pos = atomicAdd(&g_bcnt[ci], 1);  // < 1000 always
            g_bstage[(size_t)ci * BCAP + pos] = ((u64)sb << 10) | (u32)(1023 - n);
            atomicAdd(&g_hist[b * NB + bkt(sb)], 1u);
        }
    }
}

// ---------------------------------------------------------------------------
// warp 0 helper: suffix-scan a 128-bucket histogram (4 buckets/lane).
// Returns, per lane 0 only, the chosen bucket:
//   mode 0: max(max v: suf(v) >= TARGET, min v: suf(v) <= CAND)   (candidates)
//   mode 1: max v: suf(v) >= NCAND                                (survivors)
// ---------------------------------------------------------------------------
__device__ __forceinline__ int warp_threshold(const u32* hist, int mode) {
    int lane = threadIdx.x & 31;
    u32 h[4]; u32 L = 0;
    #pragma unroll
    for (int q = 0; q < 4; q++) { h[q] = hist[lane * 4 + q]; L += h[q]; }

    u32 x = L;                                    // inclusive suffix over lanes
    #pragma unroll
    for (int off = 1; off < 32; off <<= 1) {
        u32 t = __shfl_down_sync(0xffffffffu, x, off);
        if (lane + off < 32) x += t;
    }
    u32 run = x - L;                              // suffix strictly after chunk
    int t1 = 0, t2 = NB - 1;
    #pragma unroll
    for (int q = 3; q >= 0; q--) {
        u32 suf = run + h[q];
        int v = lane * 4 + q;
        if (mode == 0) {
            if (suf >= TARGET && v > t1) t1 = v;
            if (suf <= CAND   && v < t2) t2 = v;
        } else {
            if (suf >= NCAND  && v > t1) t1 = v;
        }
        run = suf;
    }
    #pragma unroll
    for (int off = 16; off; off >>= 1) {
        int a = __shfl_xor_sync(0xffffffffu, t1, off);
        int bb = __shfl_xor_sync(0xffffffffu, t2, off);
        t1 = a > t1 ? a : t1;
        t2 = bb < t2 ? bb : t2;
    }
    return (mode == 0) ? (t1 > t2 ? t1 : t2) : t1;
}

// ---------------------------------------------------------------------------
// K2: per (b, class) — in-block threshold, filter, sort, decode, NMS,
// emit survivors. grid = BATCH*NCLS, block = 128.
// ---------------------------------------------------------------------------
__global__ __launch_bounds__(128) void class_nms_kernel(
        const float* __restrict__ box,
        const float* __restrict__ anc,
        const float* __restrict__ info) {
    __shared__ u64 skey[BCAP];
    __shared__ float4 sbx[BCAP];
    __shared__ unsigned char sflag[BCAP];
    __shared__ int s_n, s_cnt, s_base, s_tb;

    int tid = threadIdx.x;
    int ci  = blockIdx.x;
    int b   = ci / NCLS;
    int c   = ci % NCLS;

    if (tid == 0) s_n = 0;
    // warp 0: candidate threshold bucket (redundant per block; deterministic)
    if (tid < 32) {
        int tb = warp_threshold(g_hist + b * NB, 0);
        if (tid == 0) s_tb = tb;
    }
    __syncthreads();

    // filter staged keys by threshold bucket
    int m  = g_bcnt[ci];
    int tb = s_tb;
    for (int i = tid; i < m; i += 128) {
        u64 k = g_bstage[(size_t)ci * BCAP + i];
        if (bkt((u32)(k >> 10)) >= tb) {
            int p = atomicAdd(&s_n, 1);
            skey[p] = k;
        }
    }
    __syncthreads();
    int n = s_n;
    if (tid == 0) g_bcnt[ci] = 0;          // cleanup for next invocation
    if (n == 0) return;

    // pad to pow2, bitonic sort descending (score, ~boxidx)
    int P = 32; while (P < n) P <<= 1;
    for (int e = tid; e < P; e += 128) if (e >= n) skey[e] = 0ull;
    for (unsigned k = 2; k <= (unsigned)P; k <<= 1) {
        for (unsigned j = k >> 1; j > 0; j >>= 1) {
            __syncthreads();
            for (int e = tid; e < P; e += 128) {
                int ixj = e ^ (int)j;
                if (ixj > e) {
                    u64 va = skey[e], vb = skey[ixj];
                    bool desc = ((e & (int)k) == 0);
                    if (desc ? (va < vb) : (va > vb)) { skey[e] = vb; skey[ixj] = va; }
                }
            }
        }
    }
    __syncthreads();

    // decode boxes (rank order)
    float hmax = info[b * 5 + 0] - 1.f;
    float wmax = info[b * 5 + 1] - 1.f;
    for (int i = tid; i < n; i += 128) {
        u64 k = skey[i];
        int nb = 1023 - (int)(k & 0x3FFull);
        float4 a = *(const float4*)(anc + (size_t)(b * NBOX + nb) * 4);
        float ha  = a.z - a.x + 1.f;
        float wa  = a.w - a.y + 1.f;
        float cya = a.x + 0.5f * ha;
        float cxa = a.y + 0.5f * wa;
        float4 e = *(const float4*)(box + ((size_t)(b * NBOX + nb) * 81 + (c + 1)) * 4);
        float cy = (e.x / 10.f) * ha + cya;
        float cx = (e.y / 10.f) * wa + cxa;
        float h  = expf(e.z / 5.f) * ha;
        float wd = expf(e.w / 5.f) * wa;
        float ymin = fminf(fmaxf(cy - 0.5f * h,        0.f), hmax);
        float ymax = fminf(fmaxf(cy + 0.5f * h - 1.f,  0.f), hmax);
        float xmin = fminf(fmaxf(cx - 0.5f * wd,       0.f), wmax);
        float xmax = fminf(fmaxf(cx + 0.5f * wd - 1.f, 0.f), wmax);
        sbx[i]   = make_float4(ymin, xmin, ymax, xmax);
        sflag[i] = 0;
    }
    __syncthreads();

    // greedy NMS: warp 0, serial over i, j-parallel over lanes
    if (tid < 32) {
        for (int i = 0; i < n - 1; i++) {
            if (sflag[i] == 0) {
                float4 B = sbx[i];
                float ai = (B.z - B.x) * (B.w - B.y);
                for (int j = i + 1 + tid; j < n; j += 32) {
                    float4 C = sbx[j];
                    float iy = fmaxf(0.f, fminf(B.z, C.z) - fmaxf(B.x, C.x));
                    float ix = fmaxf(0.f, fminf(B.w, C.w) - fmaxf(B.y, C.y));
                    float inter = iy * ix;
                    float aj  = (C.z - C.x) * (C.w - C.y);
                    float iou = inter / fmaxf(ai + aj - inter, 1e-8f);  // exact ref
                    if (iou > 0.5f) sflag[j] = 1;
                }
            }
            __syncwarp();
        }
    }
    __syncthreads();

    // reserve global survivor slots
    if (tid == 0) s_cnt = 0;
    __syncthreads();
    int my = 0;
    for (int e = tid; e < n; e += 128) if (!sflag[e]) my++;
    if (my) atomicAdd(&s_cnt, my);
    __syncthreads();
    if (tid == 0) s_base = atomicAdd(&g_scnt2[b], s_cnt);
    __syncthreads();
    if (tid == 0) s_cnt = 0;
    __syncthreads();

    // emit survivors: key (score desc, (c,rank) asc proxy), box, histogram
    for (int e = tid; e < n; e += 128) {
        if (!sflag[e]) {
            u32 sb   = (u32)(skey[e] >> 10);
            u32 flat = (u32)(c * BCAP + e);            // rank == true class rank
            int slot = atomicAdd(&s_cnt, 1);
            g_surv[b * CAND + s_base + slot] =
                ((u64)sb << 18) | (u64)(0x3FFFFu ^ flat);
            g_cbox[(size_t)ci * BCAP + e] = sbx[e];
            atomicAdd(&g_hist2[b * NB + bkt(sb)], 1u);
        }
    }
}

// ---------------------------------------------------------------------------
// K3: per batch — survivor threshold for top-100, small sort, emit output,
// all cleanup. grid = BATCH, block = 256.
// ---------------------------------------------------------------------------
__global__ __launch_bounds__(256) void final_kernel(float* __restrict__ out) {
    __shared__ u64 skey[CAND];
    __shared__ int s_tb, s_n;

    int tid = threadIdx.x;
    int b   = blockIdx.x;

    if (tid == 0) s_n = 0;
    if (tid < 32) {
        int tb = warp_threshold(g_hist2 + b * NB, 1);
        if (tid == 0) s_tb = tb;
    }
    __syncthreads();

    u32 tb2 = (u32)s_tb;

    // filter survivors above the bucket threshold
    int tot = g_scnt2[b];
    for (int i = tid; i < tot; i += 256) {
        u64 k = g_surv[b * CAND + i];
        if (bkt((u32)(k >> 18)) >= (int)tb2) {
            int p = atomicAdd(&s_n, 1);
            skey[p] = k;                      // <= CAND by construction
        }
    }
    __syncthreads();
    int n = s_n;                              // typ. ~100-200

    int P = 128; while (P < n) P <<= 1;       // <= CAND
    for (int e = tid; e < P; e += 256) if (e >= n) skey[e] = 0ull;
    for (unsigned k = 2; k <= (unsigned)P; k <<= 1) {
        for (unsigned j = k >> 1; j > 0; j >>= 1) {
            __syncthreads();
            for (int e = tid; e < P; e += 256) {
                int ixj = e ^ (int)j;
                if (ixj > e) {
                    u64 va = skey[e], vb = skey[ixj];
                    bool desc = ((e & (int)k) == 0);
                    if (desc ? (va < vb) : (va > vb)) { skey[e] = vb; skey[ixj] = va; }
                }
            }
        }
    }
    __syncthreads();

    // emit top-100
    if (tid < NCAND) {
        u64 kv   = skey[tid];
        u32 sb   = (u32)(kv >> 18);
        u32 flat = 0x3FFFFu ^ ((u32)kv & 0x3FFFFu);
        int c    = (int)(flat >> 10);
        int rank = (int)(flat & (BCAP - 1));
        float4 bx = g_cbox[(size_t)(b * NCLS + c) * BCAP + rank];
        float* o = out + (size_t)(b * NCAND + tid) * 6;
        o[0] = bx.x; o[1] = bx.y; o[2] = bx.z; o[3] = bx.w;
        o[4] = __uint_as_float(sb);
        o[5] = (float)(c + 1);
    }

    // cleanup for next invocation
    if (tid < NB) {
        g_hist [b * NB + tid] = 0;
        g_hist2[b * NB + tid] = 0;
    }
    if (tid == 0) g_scnt2[b] = 0;
}

// ---------------------------------------------------------------------------
extern "C" void kernel_launch(void* const* d_in, const int* in_sizes, int n_in,
                              void* d_out, int out_size) {
    const float* cls  = (const float*)d_in[0];
    const float* box  = (const float*)d_in[1];
    const float* anc  = (const float*)d_in[2];
    const float* info = (const float*)d_in[3];

    score_kernel<<<(BATCH * NBOX * 32 + 255) / 256, 256>>>(cls);
    class_nms_kernel<<<BATCH * NCLS, 128>>>(box, anc, info);
    final_kernel<<<BATCH, 256>>>((float*)d_out);
}